// round 7
// baseline (speedup 1.0000x reference)
#include <cuda_runtime.h>

// DotProductAttention: B=4, H=8, S=2048, D=16, fp32.
// logits = 10*tanh(QK^T*SCALE); mask(b,key)==1 -> -1e10; softmax; O = P@V.
//
// R6 design:
//  - FFMA2 (fma.rn.f32x2): pack the thread's two queries into f32x2 lanes.
//    K/V smem tiles stored PRE-DUPLICATED (k,k) as u64 so packed operands load
//    directly (no per-key broadcast MOVs). 2x fp32 FMA throughput, exact .rn.
//  - Compacted unmasked-key list per batch (parallel 512-thread scan pre-pass).
//  - Fixed softmax max = 10 => p = exp2(C2/(exp2(C1*q.k)+1)); associative
//    => split-K x8 + deterministic reduce.

#define S_LEN   2048
#define D_DIM   16
#define H_NUM   8
#define B_NUM   4
#define NQ      65536          // B*H*S
#define QT      128            // threads per block
#define QPB     256            // queries per block (2/thread)
#define KT      128            // key tile
#define SPLIT   8
#define KROW    18             // padded u64 row stride (144B: 16B-aligned, 4-way STS)

// C1 = 2*SCALE*log2(e),  C2 = -2*CLIP*log2(e)
#define C1_F  1.1047800f
#define C2_F  (-28.85390082f)

typedef unsigned long long u64;

__device__ float g_pacc[(size_t)SPLIT * NQ * D_DIM];  // 33.5 MB
__device__ float g_psum[(size_t)SPLIT * NQ];          //  2.0 MB
__device__ int   g_kidx[B_NUM][S_LEN];
__device__ int   g_kcnt[B_NUM];

__device__ __forceinline__ float ex2f(float x) {
    float r; asm("ex2.approx.ftz.f32 %0, %1;" : "=f"(r) : "f"(x)); return r;
}
__device__ __forceinline__ float rcpf(float x) {
    float r; asm("rcp.approx.ftz.f32 %0, %1;" : "=f"(r) : "f"(x)); return r;
}
__device__ __forceinline__ u64 pack2(float lo, float hi) {
    u64 r; asm("mov.b64 %0, {%1, %2};" : "=l"(r) : "f"(lo), "f"(hi)); return r;
}
__device__ __forceinline__ void unpack2(u64 v, float& lo, float& hi) {
    asm("mov.b64 {%0, %1}, %2;" : "=f"(lo), "=f"(hi) : "l"(v));
}
__device__ __forceinline__ u64 fma2(u64 a, u64 b, u64 c) {
    u64 d; asm("fma.rn.f32x2 %0, %1, %2, %3;" : "=l"(d) : "l"(a), "l"(b), "l"(c)); return d;
}
__device__ __forceinline__ u64 mul2(u64 a, u64 b) {
    u64 d; asm("mul.rn.f32x2 %0, %1, %2;" : "=l"(d) : "l"(a), "l"(b)); return d;
}
__device__ __forceinline__ u64 add2(u64 a, u64 b) {
    u64 d; asm("add.rn.f32x2 %0, %1, %2;" : "=l"(d) : "l"(a), "l"(b)); return d;
}

// ---- Pre-pass: per-batch compacted unmasked-key list. 1 block/batch, 16 warps. ----
__global__ __launch_bounds__(512)
void compact_kernel(const int* __restrict__ mask)
{
    __shared__ int wcnt[16];
    const int b    = blockIdx.x;
    const int w    = threadIdx.x >> 5;     // 0..15, each owns 128 keys
    const int lane = threadIdx.x & 31;
    const int* Mb  = mask + (size_t)b * S_LEN;
    const int keybase = w * 128;

    unsigned bals[4];
    int cnt = 0;
#pragma unroll
    for (int r = 0; r < 4; r++) {
        int key = keybase + r * 32 + lane;
        bool keep = (Mb[key] == 0);
        unsigned bal = __ballot_sync(0xffffffffu, keep);
        bals[r] = bal;
        cnt += __popc(bal);
    }
    if (lane == 0) wcnt[w] = cnt;
    __syncthreads();

    int base = 0;
    for (int i = 0; i < w; i++) base += wcnt[i];
#pragma unroll
    for (int r = 0; r < 4; r++) {
        int key = keybase + r * 32 + lane;
        unsigned bal = bals[r];
        if ((bal >> lane) & 1u)
            g_kidx[b][base + __popc(bal & ((1u << lane) - 1u))] = key;
        base += __popc(bal);
    }
    if (w == 15 && lane == 0) g_kcnt[b] = base;   // total
}

// ---- Dense inner body: j = compacted slot; all operands f32x2-packed. ----
#define ATTN_BODY(j)                                                               \
{                                                                                  \
    u64 kd[16];                                                                    \
    {                                                                              \
        const ulonglong2* kp2 = reinterpret_cast<const ulonglong2*>(Ksd + (size_t)(j) * KROW); \
        _Pragma("unroll")                                                          \
        for (int i = 0; i < 8; i++) { ulonglong2 t = kp2[i]; kd[2*i] = t.x; kd[2*i+1] = t.y; } \
    }                                                                              \
    u64 t0 = mul2(qp[0], kd[0]);                                                   \
    u64 t1 = mul2(qp[1], kd[1]);                                                   \
    u64 t2 = mul2(qp[2], kd[2]);                                                   \
    u64 t3 = mul2(qp[3], kd[3]);                                                   \
    _Pragma("unroll")                                                              \
    for (int d = 4; d < 16; d += 4) {                                              \
        t0 = fma2(qp[d+0], kd[d+0], t0);                                           \
        t1 = fma2(qp[d+1], kd[d+1], t1);                                           \
        t2 = fma2(qp[d+2], kd[d+2], t2);                                           \
        t3 = fma2(qp[d+3], kd[d+3], t3);                                           \
    }                                                                              \
    u64 dd = add2(add2(t0, t1), add2(t2, t3));                                     \
    float dA, dB; unpack2(dd, dA, dB);                                             \
    float uA = ex2f(dA), uB = ex2f(dB);                                            \
    float pA = ex2f(C2_F * rcpf(uA + 1.0f));                                       \
    float pB = ex2f(C2_F * rcpf(uB + 1.0f));                                       \
    sumA += pA; sumB += pB;                                                        \
    u64 pp = pack2(pA, pB);                                                        \
    {                                                                              \
        const ulonglong2* vp2 = reinterpret_cast<const ulonglong2*>(Vsd + (size_t)(j) * KROW); \
        _Pragma("unroll")                                                          \
        for (int i = 0; i < 8; i++) {                                              \
            ulonglong2 t = vp2[i];                                                 \
            accp[2*i]   = fma2(pp, t.x, accp[2*i]);                                \
            accp[2*i+1] = fma2(pp, t.y, accp[2*i+1]);                              \
        }                                                                          \
    }                                                                              \
}

__global__ __launch_bounds__(QT)
void attn_partial_kernel(const float* __restrict__ Q,
                         const float* __restrict__ K,
                         const float* __restrict__ V)
{
    __shared__ u64 Ksd[KT * KROW];   // duplicated (k,k) pairs, 18 KB
    __shared__ u64 Vsd[KT * KROW];   // duplicated (v,v) pairs, 18 KB

    const int bh    = blockIdx.y;      // 0..31
    const int b     = bh >> 3;         // H = 8
    const int split = blockIdx.z;      // 0..7
    const int tid   = threadIdx.x;
    const int qA    = blockIdx.x * QPB + tid;
    const int qB    = qA + QT;

    const float* Kb = K + (size_t)bh * S_LEN * D_DIM;
    const float* Vb = V + (size_t)bh * S_LEN * D_DIM;

    const int cnt     = g_kcnt[b];
    const int n_tiles = (cnt + KT - 1) / KT;
    const int tps     = (n_tiles + SPLIT - 1) / SPLIT;
    const int t_beg   = split * tps;
    const int t_end   = min(t_beg + tps, n_tiles);

    // Packed queries: qp[d] = (qA_d, qB_d) * C1.
    u64 qp[D_DIM];
    {
        const float4* pa = reinterpret_cast<const float4*>(Q + ((size_t)bh * S_LEN + qA) * D_DIM);
        const float4* pb = reinterpret_cast<const float4*>(Q + ((size_t)bh * S_LEN + qB) * D_DIM);
#pragma unroll
        for (int i = 0; i < 4; i++) {
            float4 ta = pa[i], tb = pb[i];
            qp[4*i+0] = pack2(ta.x * C1_F, tb.x * C1_F);
            qp[4*i+1] = pack2(ta.y * C1_F, tb.y * C1_F);
            qp[4*i+2] = pack2(ta.z * C1_F, tb.z * C1_F);
            qp[4*i+3] = pack2(ta.w * C1_F, tb.w * C1_F);
        }
    }

    u64 accp[D_DIM];
    const u64 zz = pack2(0.0f, 0.0f);
#pragma unroll
    for (int d = 0; d < D_DIM; d++) accp[d] = zz;
    float sumA = 0.0f, sumB = 0.0f;

    for (int t = t_beg; t < t_end; t++) {
        const int base = t * KT;
        const int nv   = min(KT, cnt - base);
        __syncthreads();
        if (tid < nv) {
            const int j = g_kidx[b][base + tid];
            const float4* kp = reinterpret_cast<const float4*>(Kb + (size_t)j * D_DIM);
            const float4* vp = reinterpret_cast<const float4*>(Vb + (size_t)j * D_DIM);
            ulonglong2* kdst = reinterpret_cast<ulonglong2*>(Ksd + (size_t)tid * KROW);
            ulonglong2* vdst = reinterpret_cast<ulonglong2*>(Vsd + (size_t)tid * KROW);
#pragma unroll
            for (int i = 0; i < 4; i++) {
                float4 tk = kp[i], tv = vp[i];
                kdst[2*i+0] = make_ulonglong2(pack2(tk.x, tk.x), pack2(tk.y, tk.y));
                kdst[2*i+1] = make_ulonglong2(pack2(tk.z, tk.z), pack2(tk.w, tk.w));
                vdst[2*i+0] = make_ulonglong2(pack2(tv.x, tv.x), pack2(tv.y, tv.y));
                vdst[2*i+1] = make_ulonglong2(pack2(tv.z, tv.z), pack2(tv.w, tv.w));
            }
        }
        __syncthreads();

        if (nv == KT) {
#pragma unroll 4
            for (int j = 0; j < KT; j++) ATTN_BODY(j);
        } else {
            for (int j = 0; j < nv; j++) ATTN_BODY(j);
        }
    }

    // Write partials (unnormalized).
    const int qiA = bh * S_LEN + qA;
    const int qiB = bh * S_LEN + qB;
    g_psum[(size_t)split * NQ + qiA] = sumA;
    g_psum[(size_t)split * NQ + qiB] = sumB;
    float4* paccA = reinterpret_cast<float4*>(g_pacc + ((size_t)split * NQ + qiA) * D_DIM);
    float4* paccB = reinterpret_cast<float4*>(g_pacc + ((size_t)split * NQ + qiB) * D_DIM);
#pragma unroll
    for (int i = 0; i < 4; i++) {
        float a0, b0, a1, b1, a2, b2, a3, b3;
        unpack2(accp[4*i+0], a0, b0);
        unpack2(accp[4*i+1], a1, b1);
        unpack2(accp[4*i+2], a2, b2);
        unpack2(accp[4*i+3], a3, b3);
        paccA[i] = make_float4(a0, a1, a2, a3);
        paccB[i] = make_float4(b0, b1, b2, b3);
    }
}

__global__ __launch_bounds__(256)
void attn_reduce_kernel(float* __restrict__ O)
{
    const int q = blockIdx.x * 256 + threadIdx.x;   // 0..NQ-1
    float sum = 0.0f;
    float4 a0 = make_float4(0,0,0,0), a1 = a0, a2 = a0, a3 = a0;
#pragma unroll
    for (int s = 0; s < SPLIT; s++) {
        sum += g_psum[(size_t)s * NQ + q];
        const float4* p = reinterpret_cast<const float4*>(g_pacc + ((size_t)s * NQ + q) * D_DIM);
        float4 t0 = p[0], t1 = p[1], t2 = p[2], t3 = p[3];
        a0.x += t0.x; a0.y += t0.y; a0.z += t0.z; a0.w += t0.w;
        a1.x += t1.x; a1.y += t1.y; a1.z += t1.z; a1.w += t1.w;
        a2.x += t2.x; a2.y += t2.y; a2.z += t2.z; a2.w += t2.w;
        a3.x += t3.x; a3.y += t3.y; a3.z += t3.z; a3.w += t3.w;
    }
    float inv = 1.0f / sum;
    float4* op = reinterpret_cast<float4*>(O + (size_t)q * D_DIM);
    op[0] = make_float4(a0.x*inv, a0.y*inv, a0.z*inv, a0.w*inv);
    op[1] = make_float4(a1.x*inv, a1.y*inv, a1.z*inv, a1.w*inv);
    op[2] = make_float4(a2.x*inv, a2.y*inv, a2.z*inv, a2.w*inv);
    op[3] = make_float4(a3.x*inv, a3.y*inv, a3.z*inv, a3.w*inv);
}

extern "C" void kernel_launch(void* const* d_in, const int* in_sizes, int n_in,
                              void* d_out, int out_size)
{
    const float* Q = (const float*)d_in[0];
    const float* K = (const float*)d_in[1];
    const float* V = (const float*)d_in[2];
    const int* mask = (const int*)d_in[3];
    float* O = (float*)d_out;

    compact_kernel<<<B_NUM, 512>>>(mask);
    dim3 grid(S_LEN / QPB, B_NUM * H_NUM, SPLIT);   // (8, 32, 8)
    attn_partial_kernel<<<grid, QT>>>(Q, K, V);
    attn_reduce_kernel<<<NQ / 256, 256>>>(O);
}

// round 11
// speedup vs baseline: 3.7033x; 3.7033x over previous
#include <cuda_runtime.h>
#include <cuda_bf16.h>
#include <cstdint>

// DotProductAttention B=4,H=8,S=2048,D=16 fp32 — mma.sync (HMMA bf16) flash kernel.
// logits = 10*tanh(QK^T*SCALE); mask(b,key)==1 -> -inf; softmax; O = P@V.
// Fixed softmax max = 10 (tanh bounded): p = exp2(C2 * rcp(exp2(C1*q.k)+1)).
// bf16 hi/lo exact split (hi=rn(x), lo=rn(x-hi)) for Q,K,P,V; 3 cross terms/GEMM.
// R10 = R9 with KSTRIDE 72->80 (16B alignment for STS.128; still bank-conflict-free).

#define S_LEN   2048
#define D_DIM   16
#define H_NUM   8
#define B_NUM   4
#define KT      128
#define THREADS 128

#define C1_F  1.1047800f       // 2*SCALE*log2(e)
#define C2_F  (-28.85390082f)  // -2*CLIP*log2(e)

// smem strides (bytes): 16B-aligned AND bank-conflict-free for fragment loads
#define KSTRIDE 80             // per key: 16 bf16 hi (32B) + 16 bf16 lo (32B), pad to 80
#define VSTRIDE 272            // Vt row: 128 keys x bf16 (256B), pad to 272

__device__ int g_kidx[B_NUM][S_LEN];
__device__ int g_kcnt[B_NUM];

__device__ __forceinline__ float ex2f(float x){ float r; asm("ex2.approx.ftz.f32 %0, %1;":"=f"(r):"f"(x)); return r; }
__device__ __forceinline__ float rcpf(float x){ float r; asm("rcp.approx.ftz.f32 %0, %1;":"=f"(r):"f"(x)); return r; }

// split (f0,f1) into packed bf16x2 hi (rn) and bf16x2 lo (rn of residual).
__device__ __forceinline__ void bsplit2(float f0, float f1, uint32_t& hi, uint32_t& lo){
    uint32_t h;
    asm("cvt.rn.bf16x2.f32 %0, %1, %2;" : "=r"(h) : "f"(f1), "f"(f0));   // low16=f0, high16=f1
    float fh0 = __uint_as_float(h << 16);
    float fh1 = __uint_as_float(h & 0xffff0000u);
    float l0 = f0 - fh0, l1 = f1 - fh1;
    uint32_t l;
    asm("cvt.rn.bf16x2.f32 %0, %1, %2;" : "=r"(l) : "f"(l1), "f"(l0));
    hi = h; lo = l;
}

__device__ __forceinline__ void mma16816(float* c, const uint32_t* a, uint32_t b0, uint32_t b1){
    asm volatile("mma.sync.aligned.m16n8k16.row.col.f32.bf16.bf16.f32 "
        "{%0,%1,%2,%3}, {%4,%5,%6,%7}, {%8,%9}, {%0,%1,%2,%3};"
        : "+f"(c[0]), "+f"(c[1]), "+f"(c[2]), "+f"(c[3])
        : "r"(a[0]), "r"(a[1]), "r"(a[2]), "r"(a[3]), "r"(b0), "r"(b1));
}

// ---- Pre-pass: per-batch compacted unmasked-key list (1 block/batch, 16 warps). ----
__global__ __launch_bounds__(512)
void compact_kernel(const int* __restrict__ mask)
{
    __shared__ int wcnt[16];
    const int b = blockIdx.x, w = threadIdx.x >> 5, lane = threadIdx.x & 31;
    const int* Mb = mask + (size_t)b * S_LEN;
    const int keybase = w * 128;
    unsigned bals[4]; int cnt = 0;
#pragma unroll
    for (int r = 0; r < 4; r++) {
        bool keep = (Mb[keybase + r * 32 + lane] == 0);
        unsigned bal = __ballot_sync(0xffffffffu, keep);
        bals[r] = bal; cnt += __popc(bal);
    }
    if (lane == 0) wcnt[w] = cnt;
    __syncthreads();
    int base = 0;
    for (int i = 0; i < w; i++) base += wcnt[i];
#pragma unroll
    for (int r = 0; r < 4; r++) {
        unsigned bal = bals[r];
        if ((bal >> lane) & 1u)
            g_kidx[b][base + __popc(bal & ((1u << lane) - 1u))] = keybase + r * 32 + lane;
        base += __popc(bal);
    }
    if (w == 15 && lane == 0) g_kcnt[b] = base;
}

__global__ __launch_bounds__(THREADS)
void attn_mma_kernel(const float* __restrict__ Q, const float* __restrict__ K,
                     const float* __restrict__ V, float* __restrict__ O)
{
    __shared__ __align__(16) unsigned char sK[KT * KSTRIDE];   // 10240 B
    __shared__ __align__(16) unsigned char sV[32 * VSTRIDE];   // 8704 B: rows d0-15 hi, d16-31 lo

    const int tid  = threadIdx.x;
    const int warp = tid >> 5, lane = tid & 31;
    const int g    = lane >> 2, tig = lane & 3;
    const int bh   = blockIdx.y, b = bh >> 3;
    const int qw   = blockIdx.x * THREADS + warp * 32;

    const float* Kb = K + (size_t)bh * S_LEN * D_DIM;
    const float* Vb = V + (size_t)bh * S_LEN * D_DIM;
    const int* kidx = g_kidx[b];
    const int cnt   = g_kcnt[b];
    const int T     = (cnt + KT - 1) / KT;

    // ---- Q fragments (A of GEMM1), pre-scaled by C1, hi/lo split ----
    uint32_t qh[2][4], ql[2][4];
#pragma unroll
    for (int mb = 0; mb < 2; mb++) {
        const float* q0 = Q + ((size_t)bh * S_LEN + qw + mb * 16 + g) * D_DIM;
        const float* q1 = q0 + 8 * D_DIM;
        float2 f00 = *(const float2*)(q0 + 2 * tig);
        float2 f10 = *(const float2*)(q1 + 2 * tig);
        float2 f01 = *(const float2*)(q0 + 2 * tig + 8);
        float2 f11 = *(const float2*)(q1 + 2 * tig + 8);
        bsplit2(f00.x * C1_F, f00.y * C1_F, qh[mb][0], ql[mb][0]);
        bsplit2(f10.x * C1_F, f10.y * C1_F, qh[mb][1], ql[mb][1]);
        bsplit2(f01.x * C1_F, f01.y * C1_F, qh[mb][2], ql[mb][2]);
        bsplit2(f11.x * C1_F, f11.y * C1_F, qh[mb][3], ql[mb][3]);
    }

    float oc[2][2][4];
#pragma unroll
    for (int mb = 0; mb < 2; mb++)
#pragma unroll
        for (int nd = 0; nd < 2; nd++)
#pragma unroll
            for (int i = 0; i < 4; i++) oc[mb][nd][i] = 0.0f;
    float s00 = 0.f, s01 = 0.f, s10 = 0.f, s11 = 0.f;   // row sums [mb][rowhalf]

    for (int t = 0; t < T; t++) {
        __syncthreads();
        // ---- load tile: thread owns compacted key slot tid ----
        {
            const int idx = t * KT + tid;
            float kv[16], vv[16];
            if (idx < cnt) {
                const int j = kidx[idx];
                const float4* kp = (const float4*)(Kb + (size_t)j * D_DIM);
                const float4* vp = (const float4*)(Vb + (size_t)j * D_DIM);
#pragma unroll
                for (int i = 0; i < 4; i++) {
                    float4 tk = kp[i], tv = vp[i];
                    kv[4*i+0]=tk.x; kv[4*i+1]=tk.y; kv[4*i+2]=tk.z; kv[4*i+3]=tk.w;
                    vv[4*i+0]=tv.x; vv[4*i+1]=tv.y; vv[4*i+2]=tv.z; vv[4*i+3]=tv.w;
                }
            } else {
#pragma unroll
                for (int i = 0; i < 16; i++) { kv[i] = 0.f; vv[i] = 0.f; }
            }
            uint32_t khi[8], klo[8];
#pragma unroll
            for (int i = 0; i < 8; i++) bsplit2(kv[2*i], kv[2*i+1], khi[i], klo[i]);
            uint4* kd = (uint4*)(sK + tid * KSTRIDE);
            kd[0] = make_uint4(khi[0], khi[1], khi[2], khi[3]);
            kd[1] = make_uint4(khi[4], khi[5], khi[6], khi[7]);
            kd[2] = make_uint4(klo[0], klo[1], klo[2], klo[3]);
            kd[3] = make_uint4(klo[4], klo[5], klo[6], klo[7]);
#pragma unroll
            for (int d = 0; d < 16; d++) {
                float f = vv[d];
                __nv_bfloat16 h = __float2bfloat16(f);
                float fh = __bfloat162float(h);
                __nv_bfloat16 l = __float2bfloat16(f - fh);
                *(unsigned short*)(sV + d * VSTRIDE + tid * 2)        = __bfloat16_as_ushort(h);
                *(unsigned short*)(sV + (d + 16) * VSTRIDE + tid * 2) = __bfloat16_as_ushort(l);
            }
        }
        __syncthreads();

        const bool full = (t + 1) * KT <= cnt;
        const int  kb0  = t * KT + 2 * tig;

#pragma unroll
        for (int j = 0; j < 8; j++) {
            // ---- K B-frags: key = 16j + nb*8 + g, pairs along d ----
            const unsigned char* ka = sK + (16 * j + g) * KSTRIDE + tig * 4;
            uint32_t kh0a = *(const uint32_t*)(ka);
            uint32_t kh0b = *(const uint32_t*)(ka + 16);
            uint32_t kl0a = *(const uint32_t*)(ka + 32);
            uint32_t kl0b = *(const uint32_t*)(ka + 48);
            uint32_t kh1a = *(const uint32_t*)(ka + 8 * KSTRIDE);
            uint32_t kh1b = *(const uint32_t*)(ka + 8 * KSTRIDE + 16);
            uint32_t kl1a = *(const uint32_t*)(ka + 8 * KSTRIDE + 32);
            uint32_t kl1b = *(const uint32_t*)(ka + 8 * KSTRIDE + 48);

            float c[2][2][4];
#pragma unroll
            for (int mb = 0; mb < 2; mb++) {
#pragma unroll
                for (int nb = 0; nb < 2; nb++)
#pragma unroll
                    for (int i = 0; i < 4; i++) c[mb][nb][i] = 0.0f;
                mma16816(c[mb][0], qh[mb], kh0a, kh0b);
                mma16816(c[mb][0], qh[mb], kl0a, kl0b);
                mma16816(c[mb][0], ql[mb], kh0a, kh0b);
                mma16816(c[mb][1], qh[mb], kh1a, kh1b);
                mma16816(c[mb][1], qh[mb], kl1a, kl1b);
                mma16816(c[mb][1], ql[mb], kh1a, kh1b);
            }

            // ---- epilogue: p = exp2(C2 * rcp(exp2(d)+1)); pack P hi/lo A-frags ----
            uint32_t ph[2][4], pl[2][4];
            const int kcol = kb0 + 16 * j;
#pragma unroll
            for (int mb = 0; mb < 2; mb++) {
#pragma unroll
                for (int nb = 0; nb < 2; nb++) {
                    float p0 = ex2f(C2_F * rcpf(ex2f(c[mb][nb][0]) + 1.0f));
                    float p1 = ex2f(C2_F * rcpf(ex2f(c[mb][nb][1]) + 1.0f));
                    float p2 = ex2f(C2_F * rcpf(ex2f(c[mb][nb][2]) + 1.0f));
                    float p3 = ex2f(C2_F * rcpf(ex2f(c[mb][nb][3]) + 1.0f));
                    if (!full) {
                        if (kcol + nb * 8     >= cnt) { p0 = 0.f; p2 = 0.f; }
                        if (kcol + nb * 8 + 1 >= cnt) { p1 = 0.f; p3 = 0.f; }
                    }
                    if (mb == 0) { s00 += p0 + p1; s01 += p2 + p3; }
                    else         { s10 += p0 + p1; s11 += p2 + p3; }
                    bsplit2(p0, p1, ph[mb][nb * 2 + 0], pl[mb][nb * 2 + 0]);
                    bsplit2(p2, p3, ph[mb][nb * 2 + 1], pl[mb][nb * 2 + 1]);
                }
            }

            // ---- V B-frags from transposed tile: (k=16j+2tig.., n=d=nd*8+g) ----
            const unsigned char* va = sV + g * VSTRIDE + j * 32 + tig * 4;
            uint32_t vh0a = *(const uint32_t*)(va);
            uint32_t vh0b = *(const uint32_t*)(va + 16);
            uint32_t vh1a = *(const uint32_t*)(va + 8 * VSTRIDE);
            uint32_t vh1b = *(const uint32_t*)(va + 8 * VSTRIDE + 16);
            uint32_t vl0a = *(const uint32_t*)(va + 16 * VSTRIDE);
            uint32_t vl0b = *(const uint32_t*)(va + 16 * VSTRIDE + 16);
            uint32_t vl1a = *(const uint32_t*)(va + 24 * VSTRIDE);
            uint32_t vl1b = *(const uint32_t*)(va + 24 * VSTRIDE + 16);

#pragma unroll
            for (int mb = 0; mb < 2; mb++) {
                mma16816(oc[mb][0], ph[mb], vh0a, vh0b);
                mma16816(oc[mb][0], ph[mb], vl0a, vl0b);
                mma16816(oc[mb][0], pl[mb], vh0a, vh0b);
                mma16816(oc[mb][1], ph[mb], vh1a, vh1b);
                mma16816(oc[mb][1], ph[mb], vl1a, vl1b);
                mma16816(oc[mb][1], pl[mb], vh1a, vh1b);
            }
        }
    }

    // ---- finalize: reduce row sums over the quad (lanes differing in tig) ----
    s00 += __shfl_xor_sync(0xffffffffu, s00, 1); s00 += __shfl_xor_sync(0xffffffffu, s00, 2);
    s01 += __shfl_xor_sync(0xffffffffu, s01, 1); s01 += __shfl_xor_sync(0xffffffffu, s01, 2);
    s10 += __shfl_xor_sync(0xffffffffu, s10, 1); s10 += __shfl_xor_sync(0xffffffffu, s10, 2);
    s11 += __shfl_xor_sync(0xffffffffu, s11, 1); s11 += __shfl_xor_sync(0xffffffffu, s11, 2);
    const float i00 = 1.0f / s00, i01 = 1.0f / s01, i10 = 1.0f / s10, i11 = 1.0f / s11;

#pragma unroll
    for (int mb = 0; mb < 2; mb++) {
        const float inv0 = mb ? i10 : i00;
        const float inv1 = mb ? i11 : i01;
#pragma unroll
        for (int nd = 0; nd < 2; nd++) {
            float* o0 = O + ((size_t)bh * S_LEN + qw + mb * 16 + g) * D_DIM + nd * 8 + 2 * tig;
            *(float2*)(o0)             = make_float2(oc[mb][nd][0] * inv0, oc[mb][nd][1] * inv0);
            *(float2*)(o0 + 8 * D_DIM) = make_float2(oc[mb][nd][2] * inv1, oc[mb][nd][3] * inv1);
        }
    }
}

extern "C" void kernel_launch(void* const* d_in, const int* in_sizes, int n_in,
                              void* d_out, int out_size)
{
    const float* Q = (const float*)d_in[0];
    const float* K = (const float*)d_in[1];
    const float* V = (const float*)d_in[2];
    const int* mask = (const int*)d_in[3];
    float* O = (float*)d_out;

    compact_kernel<<<B_NUM, 512>>>(mask);
    dim3 grid(S_LEN / THREADS, B_NUM * H_NUM);   // (16, 32)
    attn_mma_kernel<<<grid, THREADS>>>(Q, K, V, O);
}

// round 14
// speedup vs baseline: 3.8424x; 1.0376x over previous
#include <cuda_runtime.h>
#include <cuda_bf16.h>
#include <cstdint>

// DotProductAttention B=4,H=8,S=2048,D=16 fp32 — mma.sync (HMMA bf16) flash kernel.
// logits = 10*tanh(QK^T*SCALE); mask(b,key)==1 -> -inf; softmax; O = P@V.
// Fixed softmax max = 10 (tanh bounded): p = exp2(C2 * rcp(exp2(C1*q.k)+1)).
// bf16 hi/lo exact split (hi=rn(x), lo=rn(x-hi)) for Q,K,P,V; 3 cross terms/GEMM.
// R12 = R11 + split-K x2 (grid z): doubles resident warps (occ 19.5% was the
// limiter; issue=46%), partials to scratch + deterministic reduce kernel.

#define S_LEN   2048
#define D_DIM   16
#define H_NUM   8
#define B_NUM   4
#define NQ      65536
#define KT      128
#define THREADS 128
#define SPLIT   2

#define C1_F  1.1047800f       // 2*SCALE*log2(e)
#define C2_F  (-28.85390082f)  // -2*CLIP*log2(e)

// smem strides (bytes): 16B-aligned AND bank-conflict-free for fragment loads
#define KSTRIDE 80             // per key: 16 bf16 hi (32B) + 16 bf16 lo (32B), pad to 80
#define VSTRIDE 272            // Vt row: 128 keys x bf16 (256B), pad to 272

__device__ int   g_kidx[B_NUM][S_LEN];
__device__ int   g_kcnt[B_NUM];
__device__ float g_po[(size_t)SPLIT * NQ * D_DIM];   // 8.4 MB unnormalized partial O
__device__ float g_ps[(size_t)SPLIT * NQ];           // partial row sums

__device__ __forceinline__ float ex2f(float x){ float r; asm("ex2.approx.ftz.f32 %0, %1;":"=f"(r):"f"(x)); return r; }
__device__ __forceinline__ float rcpf(float x){ float r; asm("rcp.approx.ftz.f32 %0, %1;":"=f"(r):"f"(x)); return r; }

// split (f0,f1) into packed bf16x2 hi (rn) and bf16x2 lo (rn of residual).
__device__ __forceinline__ void bsplit2(float f0, float f1, uint32_t& hi, uint32_t& lo){
    uint32_t h;
    asm("cvt.rn.bf16x2.f32 %0, %1, %2;" : "=r"(h) : "f"(f1), "f"(f0));   // low16=f0, high16=f1
    float fh0 = __uint_as_float(h << 16);
    float fh1 = __uint_as_float(h & 0xffff0000u);
    float l0 = f0 - fh0, l1 = f1 - fh1;
    uint32_t l;
    asm("cvt.rn.bf16x2.f32 %0, %1, %2;" : "=r"(l) : "f"(l1), "f"(l0));
    hi = h; lo = l;
}

__device__ __forceinline__ void mma16816(float* c, const uint32_t* a, uint32_t b0, uint32_t b1){
    asm volatile("mma.sync.aligned.m16n8k16.row.col.f32.bf16.bf16.f32 "
        "{%0,%1,%2,%3}, {%4,%5,%6,%7}, {%8,%9}, {%0,%1,%2,%3};"
        : "+f"(c[0]), "+f"(c[1]), "+f"(c[2]), "+f"(c[3])
        : "r"(a[0]), "r"(a[1]), "r"(a[2]), "r"(a[3]), "r"(b0), "r"(b1));
}

// ---- Pre-pass: per-batch compacted unmasked-key list (1 block/batch, 16 warps). ----
__global__ __launch_bounds__(512)
void compact_kernel(const int* __restrict__ mask)
{
    __shared__ int wcnt[16];
    const int b = blockIdx.x, w = threadIdx.x >> 5, lane = threadIdx.x & 31;
    const int* Mb = mask + (size_t)b * S_LEN;
    const int keybase = w * 128;
    unsigned bals[4]; int cnt = 0;
#pragma unroll
    for (int r = 0; r < 4; r++) {
        bool keep = (Mb[keybase + r * 32 + lane] == 0);
        unsigned bal = __ballot_sync(0xffffffffu, keep);
        bals[r] = bal; cnt += __popc(bal);
    }
    if (lane == 0) wcnt[w] = cnt;
    __syncthreads();
    int base = 0;
    for (int i = 0; i < w; i++) base += wcnt[i];
#pragma unroll
    for (int r = 0; r < 4; r++) {
        unsigned bal = bals[r];
        if ((bal >> lane) & 1u)
            g_kidx[b][base + __popc(bal & ((1u << lane) - 1u))] = keybase + r * 32 + lane;
        base += __popc(bal);
    }
    if (w == 15 && lane == 0) g_kcnt[b] = base;
}

__global__ __launch_bounds__(THREADS, 6)
void attn_mma_kernel(const float* __restrict__ Q, const float* __restrict__ K,
                     const float* __restrict__ V)
{
    __shared__ __align__(16) unsigned char sK[KT * KSTRIDE];   // 10240 B
    __shared__ __align__(16) unsigned char sV[32 * VSTRIDE];   // 8704 B: rows d0-15 hi, d16-31 lo

    const int tid  = threadIdx.x;
    const int warp = tid >> 5, lane = tid & 31;
    const int g    = lane >> 2, tig = lane & 3;
    const int bh   = blockIdx.y, b = bh >> 3;
    const int z    = blockIdx.z;
    const int qw   = blockIdx.x * THREADS + warp * 32;

    const float* Kb = K + (size_t)bh * S_LEN * D_DIM;
    const float* Vb = V + (size_t)bh * S_LEN * D_DIM;
    const int* kidx = g_kidx[b];
    const int cnt   = g_kcnt[b];
    const int T     = (cnt + KT - 1) / KT;
    const int Th    = (T + 1) >> 1;
    const int t_beg = z * Th;
    const int t_end = z ? T : Th;

    // ---- Q fragments (A of GEMM1), pre-scaled by C1, hi/lo split ----
    uint32_t qh[2][4], ql[2][4];
#pragma unroll
    for (int mb = 0; mb < 2; mb++) {
        const float* q0 = Q + ((size_t)bh * S_LEN + qw + mb * 16 + g) * D_DIM;
        const float* q1 = q0 + 8 * D_DIM;
        float2 f00 = *(const float2*)(q0 + 2 * tig);
        float2 f10 = *(const float2*)(q1 + 2 * tig);
        float2 f01 = *(const float2*)(q0 + 2 * tig + 8);
        float2 f11 = *(const float2*)(q1 + 2 * tig + 8);
        bsplit2(f00.x * C1_F, f00.y * C1_F, qh[mb][0], ql[mb][0]);
        bsplit2(f10.x * C1_F, f10.y * C1_F, qh[mb][1], ql[mb][1]);
        bsplit2(f01.x * C1_F, f01.y * C1_F, qh[mb][2], ql[mb][2]);
        bsplit2(f11.x * C1_F, f11.y * C1_F, qh[mb][3], ql[mb][3]);
    }

    float oc[2][2][4];
#pragma unroll
    for (int mb = 0; mb < 2; mb++)
#pragma unroll
        for (int nd = 0; nd < 2; nd++)
#pragma unroll
            for (int i = 0; i < 4; i++) oc[mb][nd][i] = 0.0f;
    float s00 = 0.f, s01 = 0.f, s10 = 0.f, s11 = 0.f;   // row sums [mb][rowhalf]

    for (int t = t_beg; t < t_end; t++) {
        __syncthreads();
        // ---- load tile: thread owns compacted key slot tid ----
        {
            const int idx = t * KT + tid;
            float kv[16], vv[16];
            if (idx < cnt) {
                const int j = kidx[idx];
                const float4* kp = (const float4*)(Kb + (size_t)j * D_DIM);
                const float4* vp = (const float4*)(Vb + (size_t)j * D_DIM);
#pragma unroll
                for (int i = 0; i < 4; i++) {
                    float4 tk = kp[i], tv = vp[i];
                    kv[4*i+0]=tk.x; kv[4*i+1]=tk.y; kv[4*i+2]=tk.z; kv[4*i+3]=tk.w;
                    vv[4*i+0]=tv.x; vv[4*i+1]=tv.y; vv[4*i+2]=tv.z; vv[4*i+3]=tv.w;
                }
            } else {
#pragma unroll
                for (int i = 0; i < 16; i++) { kv[i] = 0.f; vv[i] = 0.f; }
            }
            uint32_t khi[8], klo[8];
#pragma unroll
            for (int i = 0; i < 8; i++) bsplit2(kv[2*i], kv[2*i+1], khi[i], klo[i]);
            uint4* kd = (uint4*)(sK + tid * KSTRIDE);
            kd[0] = make_uint4(khi[0], khi[1], khi[2], khi[3]);
            kd[1] = make_uint4(khi[4], khi[5], khi[6], khi[7]);
            kd[2] = make_uint4(klo[0], klo[1], klo[2], klo[3]);
            kd[3] = make_uint4(klo[4], klo[5], klo[6], klo[7]);
#pragma unroll
            for (int d = 0; d < 16; d++) {
                float f = vv[d];
                __nv_bfloat16 h = __float2bfloat16(f);
                float fh = __bfloat162float(h);
                __nv_bfloat16 l = __float2bfloat16(f - fh);
                *(unsigned short*)(sV + d * VSTRIDE + tid * 2)        = __bfloat16_as_ushort(h);
                *(unsigned short*)(sV + (d + 16) * VSTRIDE + tid * 2) = __bfloat16_as_ushort(l);
            }
        }
        __syncthreads();

        const bool full = (t + 1) * KT <= cnt;
        const int  kb0  = t * KT + 2 * tig;

#pragma unroll
        for (int j = 0; j < 8; j++) {
            // ---- K B-frags: key = 16j + nb*8 + g, pairs along d ----
            const unsigned char* ka = sK + (16 * j + g) * KSTRIDE + tig * 4;
            uint32_t kh0a = *(const uint32_t*)(ka);
            uint32_t kh0b = *(const uint32_t*)(ka + 16);
            uint32_t kl0a = *(const uint32_t*)(ka + 32);
            uint32_t kl0b = *(const uint32_t*)(ka + 48);
            uint32_t kh1a = *(const uint32_t*)(ka + 8 * KSTRIDE);
            uint32_t kh1b = *(const uint32_t*)(ka + 8 * KSTRIDE + 16);
            uint32_t kl1a = *(const uint32_t*)(ka + 8 * KSTRIDE + 32);
            uint32_t kl1b = *(const uint32_t*)(ka + 8 * KSTRIDE + 48);

            float c[2][2][4];
#pragma unroll
            for (int mb = 0; mb < 2; mb++) {
#pragma unroll
                for (int nb = 0; nb < 2; nb++)
#pragma unroll
                    for (int i = 0; i < 4; i++) c[mb][nb][i] = 0.0f;
                mma16816(c[mb][0], qh[mb], kh0a, kh0b);
                mma16816(c[mb][0], qh[mb], kl0a, kl0b);
                mma16816(c[mb][0], ql[mb], kh0a, kh0b);
                mma16816(c[mb][1], qh[mb], kh1a, kh1b);
                mma16816(c[mb][1], qh[mb], kl1a, kl1b);
                mma16816(c[mb][1], ql[mb], kh1a, kh1b);
            }

            // ---- epilogue: p = exp2(C2 * rcp(exp2(d)+1)); pack P hi/lo A-frags ----
            uint32_t ph[2][4], pl[2][4];
            const int kcol = kb0 + 16 * j;
#pragma unroll
            for (int mb = 0; mb < 2; mb++) {
#pragma unroll
                for (int nb = 0; nb < 2; nb++) {
                    float p0 = ex2f(C2_F * rcpf(ex2f(c[mb][nb][0]) + 1.0f));
                    float p1 = ex2f(C2_F * rcpf(ex2f(c[mb][nb][1]) + 1.0f));
                    float p2 = ex2f(C2_F * rcpf(ex2f(c[mb][nb][2]) + 1.0f));
                    float p3 = ex2f(C2_F * rcpf(ex2f(c[mb][nb][3]) + 1.0f));
                    if (!full) {
                        if (kcol + nb * 8     >= cnt) { p0 = 0.f; p2 = 0.f; }
                        if (kcol + nb * 8 + 1 >= cnt) { p1 = 0.f; p3 = 0.f; }
                    }
                    if (mb == 0) { s00 += p0 + p1; s01 += p2 + p3; }
                    else         { s10 += p0 + p1; s11 += p2 + p3; }
                    bsplit2(p0, p1, ph[mb][nb * 2 + 0], pl[mb][nb * 2 + 0]);
                    bsplit2(p2, p3, ph[mb][nb * 2 + 1], pl[mb][nb * 2 + 1]);
                }
            }

            // ---- V B-frags from transposed tile: (k=16j+2tig.., n=d=nd*8+g) ----
            const unsigned char* va = sV + g * VSTRIDE + j * 32 + tig * 4;
            uint32_t vh0a = *(const uint32_t*)(va);
            uint32_t vh0b = *(const uint32_t*)(va + 16);
            uint32_t vh1a = *(const uint32_t*)(va + 8 * VSTRIDE);
            uint32_t vh1b = *(const uint32_t*)(va + 8 * VSTRIDE + 16);
            uint32_t vl0a = *(const uint32_t*)(va + 16 * VSTRIDE);
            uint32_t vl0b = *(const uint32_t*)(va + 16 * VSTRIDE + 16);
            uint32_t vl1a = *(const uint32_t*)(va + 24 * VSTRIDE);
            uint32_t vl1b = *(const uint32_t*)(va + 24 * VSTRIDE + 16);

#pragma unroll
            for (int mb = 0; mb < 2; mb++) {
                mma16816(oc[mb][0], ph[mb], vh0a, vh0b);
                mma16816(oc[mb][0], ph[mb], vl0a, vl0b);
                mma16816(oc[mb][0], pl[mb], vh0a, vh0b);
                mma16816(oc[mb][1], ph[mb], vh1a, vh1b);
                mma16816(oc[mb][1], ph[mb], vl1a, vl1b);
                mma16816(oc[mb][1], pl[mb], vh1a, vh1b);
            }
        }
    }

    // ---- quad-reduce row sums; write unnormalized partials to scratch ----
    s00 += __shfl_xor_sync(0xffffffffu, s00, 1); s00 += __shfl_xor_sync(0xffffffffu, s00, 2);
    s01 += __shfl_xor_sync(0xffffffffu, s01, 1); s01 += __shfl_xor_sync(0xffffffffu, s01, 2);
    s10 += __shfl_xor_sync(0xffffffffu, s10, 1); s10 += __shfl_xor_sync(0xffffffffu, s10, 2);
    s11 += __shfl_xor_sync(0xffffffffu, s11, 1); s11 += __shfl_xor_sync(0xffffffffu, s11, 2);

    const size_t qbase = (size_t)z * NQ + (size_t)bh * S_LEN + qw;
    if (tig == 0) {
        g_ps[qbase + g]      = s00;
        g_ps[qbase + 8 + g]  = s01;
        g_ps[qbase + 16 + g] = s10;
        g_ps[qbase + 24 + g] = s11;
    }
#pragma unroll
    for (int mb = 0; mb < 2; mb++) {
#pragma unroll
        for (int nd = 0; nd < 2; nd++) {
            float* o0 = g_po + (qbase + mb * 16 + g) * D_DIM + nd * 8 + 2 * tig;
            *(float2*)(o0)             = make_float2(oc[mb][nd][0], oc[mb][nd][1]);
            *(float2*)(o0 + 8 * D_DIM) = make_float2(oc[mb][nd][2], oc[mb][nd][3]);
        }
    }
}

__global__ __launch_bounds__(256)
void attn_reduce_kernel(float* __restrict__ O)
{
    const int q = blockIdx.x * 256 + threadIdx.x;
    const float inv = 1.0f / (g_ps[q] + g_ps[NQ + q]);
    const float4* p0 = (const float4*)(g_po + (size_t)q * D_DIM);
    const float4* p1 = (const float4*)(g_po + ((size_t)NQ + q) * D_DIM);
    float4* op = (float4*)(O + (size_t)q * D_DIM);
#pragma unroll
    for (int i = 0; i < 4; i++) {
        float4 a = p0[i], b = p1[i];
        op[i] = make_float4((a.x + b.x) * inv, (a.y + b.y) * inv,
                            (a.z + b.z) * inv, (a.w + b.w) * inv);
    }
}

extern "C" void kernel_launch(void* const* d_in, const int* in_sizes, int n_in,
                              void* d_out, int out_size)
{
    const float* Q = (const float*)d_in[0];
    const float* K = (const float*)d_in[1];
    const float* V = (const float*)d_in[2];
    const int* mask = (const int*)d_in[3];
    float* O = (float*)d_out;

    compact_kernel<<<B_NUM, 512>>>(mask);
    dim3 grid(S_LEN / THREADS, B_NUM * H_NUM, SPLIT);   // (16, 32, 2)
    attn_mma_kernel<<<grid, THREADS>>>(Q, K, V);
    attn_reduce_kernel<<<NQ / 256, 256>>>(O);
}